// round 4
// baseline (speedup 1.0000x reference)
#include <cuda_runtime.h>
#include <cuda_bf16.h>

// LIF neuron update (SpikeLayer.update_neurons), one timestep.
// Elementwise over N = 12,845,056 fp32 elements. 5 inputs, 6 stacked outputs.
// Pure streaming: read-once inputs, write-once outputs -> .cs cache hints.
// Each thread handles 2 float4 groups (i, i+half) for MLP=10.

#define V_THRESH   1.0f
#define TIME_C     0.5f
#define REFRAC_NEW 2.5f   // TIME + TAU_REFRAC

__device__ __forceinline__ float4 ldcs4(const float4* p) {
    float4 v;
    asm volatile("ld.global.cs.v4.f32 {%0,%1,%2,%3}, [%4];"
                 : "=f"(v.x), "=f"(v.y), "=f"(v.z), "=f"(v.w) : "l"(p));
    return v;
}
__device__ __forceinline__ void stcs4(float4* p, float4 v) {
    asm volatile("st.global.cs.v4.f32 [%0], {%1,%2,%3,%4};"
                 :: "l"(p), "f"(v.x), "f"(v.y), "f"(v.z), "f"(v.w) : "memory");
}

__device__ __forceinline__ void lif_compute(
    const float4& imp, const float4& m, const float4& ma,
    const float4& ru, const float4& sc,
    float4& o_spk, float4& o_mem, float4& o_macc,
    float4& o_ru, float4& o_cnt, float4& o_st)
{
    #pragma unroll
    for (int c = 0; c < 4; c++) {
        float impv = (&imp.x)[c];
        float mv   = (&m.x)[c];
        float mav  = (&ma.x)[c];
        float ruv  = (&ru.x)[c];
        float scv  = (&sc.x)[c];

        float masked   = (ruv > TIME_C) ? 0.0f : impv;
        float new_mem  = mv + masked;
        float new_macc = mav + masked;
        bool  fire     = (new_mem >= V_THRESH);

        (&o_spk.x)[c]  = fire ? V_THRESH : 0.0f;
        (&o_mem.x)[c]  = fire ? (new_mem - V_THRESH) : new_mem;
        (&o_macc.x)[c] = new_macc;
        (&o_ru.x)[c]   = fire ? REFRAC_NEW : ruv;
        (&o_cnt.x)[c]  = scv + (fire ? 1.0f : 0.0f);
        (&o_st.x)[c]   = fire ? (V_THRESH * TIME_C) : 0.0f;
    }
}

__global__ void __launch_bounds__(256) lif_update_kernel(
    const float4* __restrict__ impulse,
    const float4* __restrict__ mem,
    const float4* __restrict__ mem_acc,
    const float4* __restrict__ refrac_until,
    const float4* __restrict__ spikecounts,
    float4* __restrict__ out,     // 6 planes of n4 float4 each
    int n4, int half)
{
    int i = blockIdx.x * blockDim.x + threadIdx.x;
    if (i >= half) return;
    int j = i + half;            // j < n4 guaranteed (n4 even)

    // Front-batch all 10 loads for max MLP.
    float4 imp0 = ldcs4(impulse      + i);
    float4 m0   = ldcs4(mem          + i);
    float4 ma0  = ldcs4(mem_acc      + i);
    float4 ru0  = ldcs4(refrac_until + i);
    float4 sc0  = ldcs4(spikecounts  + i);
    float4 imp1 = ldcs4(impulse      + j);
    float4 m1   = ldcs4(mem          + j);
    float4 ma1  = ldcs4(mem_acc      + j);
    float4 ru1  = ldcs4(refrac_until + j);
    float4 sc1  = ldcs4(spikecounts  + j);

    float4 a0, b0, c0, d0, e0, f0;
    float4 a1, b1, c1, d1, e1, f1;
    lif_compute(imp0, m0, ma0, ru0, sc0, a0, b0, c0, d0, e0, f0);
    lif_compute(imp1, m1, ma1, ru1, sc1, a1, b1, c1, d1, e1, f1);

    size_t N = (size_t)n4;
    stcs4(out + 0 * N + i, a0);  stcs4(out + 0 * N + j, a1);
    stcs4(out + 1 * N + i, b0);  stcs4(out + 1 * N + j, b1);
    stcs4(out + 2 * N + i, c0);  stcs4(out + 2 * N + j, c1);
    stcs4(out + 3 * N + i, d0);  stcs4(out + 3 * N + j, d1);
    stcs4(out + 4 * N + i, e0);  stcs4(out + 4 * N + j, e1);
    stcs4(out + 5 * N + i, f0);  stcs4(out + 5 * N + j, f1);
}

extern "C" void kernel_launch(void* const* d_in, const int* in_sizes, int n_in,
                              void* d_out, int out_size)
{
    const float* impulse      = (const float*)d_in[0];
    const float* mem          = (const float*)d_in[1];
    const float* mem_acc      = (const float*)d_in[2];
    const float* refrac_until = (const float*)d_in[3];
    const float* spikecounts  = (const float*)d_in[4];

    int n    = in_sizes[0];     // 12,845,056
    int n4   = n / 4;           // 3,211,264 (divisible by 4)
    int half = n4 / 2;          // 1,605,632

    int threads = 256;
    int blocks  = (half + threads - 1) / threads;   // 6272

    lif_update_kernel<<<blocks, threads>>>(
        (const float4*)impulse,
        (const float4*)mem,
        (const float4*)mem_acc,
        (const float4*)refrac_until,
        (const float4*)spikecounts,
        (float4*)d_out,
        n4, half);
}